// round 16
// baseline (speedup 1.0000x reference)
#include <cuda_runtime.h>
#include <math.h>
#include <stdint.h>

#define K_CTX 64
#define D_DIM 128
#define C_CAND 256
#define DS 200
#define EPS 1e-8f
#define GRID_B 146          // 110 blocks x2 cands + 36 blocks x1
#define TWO_CAND 110

// Padded row stride: 132 floats (528B, 16B-aligned); MMA frag loads conflict-free.
#define PAD_STRIDE 132
#define ROW_BYTES (PAD_STRIDE * 4)      // 528
#define AM_FLOATS (K_CTX * PAD_STRIDE)  // 8448

// Scratch (device globals)
__device__ __align__(16) float g_AM[AM_FLOATS];         // padded, tf32-rounded
__device__ __align__(16) float g_AW[K_CTX * D_DIM];     // A @ W, flat fp32

// smem: sAM(8448) sB0(8448) sB1(8448) rowP(256) colP(256) rows_w(64) cols_w(64)
//       scratch(1024) scal(8) mbars(6)
#define SMEM_FLOATS (3 * AM_FLOATS + 256 + 256 + 64 + 64 + 1024 + 8 + 6)

__device__ __forceinline__ uint32_t smem_u32(const void* p) {
    return (uint32_t)__cvta_generic_to_shared(p);
}
__device__ __forceinline__ void mbar_init(uint32_t mbar, uint32_t cnt) {
    asm volatile("mbarrier.init.shared.b64 [%0], %1;" :: "r"(mbar), "r"(cnt) : "memory");
}
__device__ __forceinline__ void mbar_expect_tx(uint32_t mbar, uint32_t bytes) {
    asm volatile("mbarrier.arrive.expect_tx.shared.b64 _, [%0], %1;"
                 :: "r"(mbar), "r"(bytes) : "memory");
}
__device__ __forceinline__ void mbar_wait(uint32_t mbar, uint32_t parity) {
    uint32_t done;
    asm volatile(
        "{\n\t.reg .pred p;\n\t"
        "mbarrier.try_wait.parity.acquire.cta.shared::cta.b64 p, [%1], %2;\n\t"
        "selp.b32 %0, 1, 0, p;\n\t}"
        : "=r"(done) : "r"(mbar), "r"(parity) : "memory");
    if (!done) {
        asm volatile(
            "{\n\t.reg .pred P1;\n\t"
            "WAIT_LOOP_%=:\n\t"
            "mbarrier.try_wait.parity.acquire.cta.shared::cta.b64 P1, [%0], %1, 0x989680;\n\t"
            "@P1 bra.uni WAIT_DONE_%=;\n\t"
            "bra.uni WAIT_LOOP_%=;\n\t"
            "WAIT_DONE_%=:\n\t}"
            :: "r"(mbar), "r"(parity) : "memory");
    }
}
__device__ __forceinline__ void bulk_g2s(uint32_t dst_smem, const void* src_gmem,
                                         uint32_t bytes, uint32_t mbar) {
    asm volatile(
        "cp.async.bulk.shared::cluster.global.mbarrier::complete_tx::bytes "
        "[%0], [%1], %2, [%3];"
        :: "r"(dst_smem), "l"(src_gmem), "r"(bytes), "r"(mbar) : "memory");
}
__device__ __forceinline__ float tanh_fast(float x) {
    float y;
    asm("tanh.approx.f32 %0, %1;" : "=f"(y) : "f"(x));
    return y;
}
__device__ __forceinline__ uint32_t to_tf32(float x) {
    uint32_t y;
    asm("cvt.rna.tf32.f32 %0, %1;" : "=r"(y) : "f"(x));
    return y;
}
__device__ __forceinline__ void mma_tf32(float* c, uint32_t a0, uint32_t a1,
                                         uint32_t a2, uint32_t a3,
                                         uint32_t b0, uint32_t b1) {
    asm volatile(
        "mma.sync.aligned.m16n8k8.row.col.f32.tf32.tf32.f32 "
        "{%0,%1,%2,%3}, {%4,%5,%6,%7}, {%8,%9}, {%0,%1,%2,%3};"
        : "+f"(c[0]), "+f"(c[1]), "+f"(c[2]), "+f"(c[3])
        : "r"(a0), "r"(a1), "r"(a2), "r"(a3), "r"(b0), "r"(b1));
}

// ---------------------------------------------------------------------------
// Kernel 1: prep — grid 128. Block b: k = b&63; mode = b>>6 (0: AM, 1: AW).
// ---------------------------------------------------------------------------
__global__ __launch_bounds__(512, 2)
void prep_kernel(const float* __restrict__ table,
                 const float* __restrict__ att_mat,
                 const float* __restrict__ W,
                 const int* __restrict__ t1_ctx) {
    __shared__ float arow[D_DIM];
    __shared__ float part[512];
    const int k    = blockIdx.x & 63;
    const int mode = blockIdx.x >> 6;
    const int tid  = threadIdx.x;

    if (tid < D_DIM)
        arow[tid] = table[(long long)t1_ctx[k] * D_DIM + tid];
    __syncthreads();
    {
        const int d = tid & 127;
        const int q = tid >> 7;
        const float* M  = (mode == 0) ? att_mat : W;
        const float* mp = M + (q * 32) * D_DIM + d;
        const float* ar = arow + q * 32;
        float acc = 0.f;
#pragma unroll
        for (int e = 0; e < 32; e++)
            acc = fmaf(ar[e], mp[e * D_DIM], acc);
        part[tid] = acc;
    }
    __syncthreads();
    if (tid < D_DIM) {
        float v = part[tid] + part[D_DIM + tid]
                + part[2 * D_DIM + tid] + part[3 * D_DIM + tid];
        if (mode == 0)
            g_AM[k * PAD_STRIDE + tid] = __uint_as_float(to_tf32(v));
        else
            g_AW[k * D_DIM + tid] = v;
    }
}

// ---------------------------------------------------------------------------
// Kernel 2: main — grid 146, block 512, 1/SM (perfect balance).
// Block b: candidate b, and (if b<110) candidate b+146 serially.
// Both B gathers + the single AM copy issued at t=0.
// ---------------------------------------------------------------------------
__global__ __launch_bounds__(512, 1)
void cand_kernel(const float* __restrict__ table,
                 const float* __restrict__ str_t1,
                 const float* __restrict__ str_t2s,
                 const float* __restrict__ b_bi,
                 const int* __restrict__ t2_ctx,
                 float* __restrict__ out) {
    extern __shared__ __align__(16) float sm[];
    float* sAM     = sm;                        // [64][132] tf32 AM
    float* sB0     = sAM + AM_FLOATS;
    float* sB1     = sB0 + AM_FLOATS;
    float* rowP    = sB1 + AM_FLOATS;           // [4][64]
    float* colP    = rowP + 256;                // [4][64]
    float* rows_w  = colP + 256;                // 64
    float* cols_w  = rows_w + K_CTX;            // 64
    float* scratch = cols_w + K_CTX;            // 1024 (tail partials)
    float* scal    = scratch + 1024;            // [2][4]
    uint64_t* mbars = (uint64_t*)(scal + 8);    // [0]=g0 [1]=g1 [2]=AM

    const int b    = blockIdx.x;
    const int nc   = (b < TWO_CAND) ? 2 : 1;
    const int c0   = b;
    const int c1   = b + GRID_B;
    const int tid  = threadIdx.x;
    const int wid  = tid >> 5;
    const int lane = tid & 31;
    const uint32_t mbar_g0 = smem_u32(&mbars[0]);
    const uint32_t mbar_g1 = smem_u32(&mbars[1]);
    const uint32_t mbar_a  = smem_u32(&mbars[2]);

    // --- phase 0: init mbars + zero accumulators ---
    if (tid == 0) {
        mbar_init(mbar_g0, 1);
        mbar_init(mbar_g1, 1);
        mbar_init(mbar_a, 1);
        mbar_expect_tx(mbar_g0, K_CTX * D_DIM * 4);
        if (nc == 2) mbar_expect_tx(mbar_g1, K_CTX * D_DIM * 4);
        mbar_expect_tx(mbar_a, AM_FLOATS * 4);
    }
    if (tid < 8) scal[tid] = 0.f;
    __syncthreads();

    // --- phase 1: issue all async copies up front ---
    const int* ctx0 = t2_ctx + c0 * K_CTX;
    const int* ctx1 = t2_ctx + c1 * K_CTX;   // valid only if nc==2
    if (tid < K_CTX) {
        bulk_g2s(smem_u32(sB0) + tid * ROW_BYTES,
                 table + (long long)ctx0[tid] * D_DIM, D_DIM * 4, mbar_g0);
    } else if (tid < 2 * K_CTX) {
        if (nc == 2) {
            int m = tid - K_CTX;
            bulk_g2s(smem_u32(sB1) + m * ROW_BYTES,
                     table + (long long)ctx1[m] * D_DIM, D_DIM * 4, mbar_g1);
        }
    } else if (tid == 2 * K_CTX) {
        bulk_g2s(smem_u32(sAM), g_AM, AM_FLOATS * 4, mbar_a);
    }

    // --- phase 2: string cosine partials for both candidates ---
    {
        int half = tid >> 8;                  // warps 0-7 -> c0, 8-15 -> c1
        int j = tid & 255;
        if (half < nc) {
            float* sc = scal + 4 * half;
            int cc = half ? c1 : c0;
            float pd = 0.f, p1 = 0.f, p2 = 0.f;
            if (j < DS) {
                float x1 = str_t1[j];
                float x2 = str_t2s[cc * DS + j];
                pd = x1 * x2; p1 = x1 * x1; p2 = x2 * x2;
            }
#pragma unroll
            for (int off = 16; off; off >>= 1) {
                pd += __shfl_down_sync(0xffffffffu, pd, off);
                p1 += __shfl_down_sync(0xffffffffu, p1, off);
                p2 += __shfl_down_sync(0xffffffffu, p2, off);
            }
            if (lane == 0 && (wid & 7) < 7) {
                atomicAdd(&sc[0], pd);
                atomicAdd(&sc[1], p1);
                atomicAdd(&sc[2], p2);
            }
        }
    }

    // --- wait for AM once ---
    mbar_wait(mbar_a, 0);

    // ======================= serial per-candidate loop =======================
#pragma unroll 1
    for (int h = 0; h < nc; h++) {
        float* sB = h ? sB1 : sB0;
        const int cc = h ? c1 : c0;
        float* sc = scal + 4 * h;

        mbar_wait(h ? mbar_g1 : mbar_g0, 0);
        __syncthreads();

        // --- sim = tanh(AM @ B^T) via m16n8k8 tf32 MMA ---
        {
            const int mt = wid & 3;
            const int g  = wid >> 2;
            const int q  = lane >> 2;
            const int r  = lane & 3;
            const float* Ab  = sAM + mt * 16 * PAD_STRIDE;
            const float* Bb0 = sB + (g * 16) * PAD_STRIDE;
            const float* Bb1 = Bb0 + 8 * PAD_STRIDE;

            float a0c[4] = {0.f, 0.f, 0.f, 0.f};
            float a1c[4] = {0.f, 0.f, 0.f, 0.f};

#pragma unroll
            for (int ks = 0; ks < 16; ks++) {
                const int kb = ks * 8;
                uint32_t a0 = __float_as_uint(Ab[q * PAD_STRIDE + kb + r]);
                uint32_t a1 = __float_as_uint(Ab[(q + 8) * PAD_STRIDE + kb + r]);
                uint32_t a2 = __float_as_uint(Ab[q * PAD_STRIDE + kb + r + 4]);
                uint32_t a3 = __float_as_uint(Ab[(q + 8) * PAD_STRIDE + kb + r + 4]);
                uint32_t b00 = to_tf32(Bb0[q * PAD_STRIDE + kb + r]);
                uint32_t b01 = to_tf32(Bb0[q * PAD_STRIDE + kb + r + 4]);
                uint32_t b10 = to_tf32(Bb1[q * PAD_STRIDE + kb + r]);
                uint32_t b11 = to_tf32(Bb1[q * PAD_STRIDE + kb + r + 4]);
                mma_tf32(a0c, a0, a1, a2, a3, b00, b01);
                mma_tf32(a1c, a0, a1, a2, a3, b10, b11);
            }

            float d00 = tanh_fast(a0c[0]), d01 = tanh_fast(a0c[1]);
            float d02 = tanh_fast(a0c[2]), d03 = tanh_fast(a0c[3]);
            float e00 = tanh_fast(a1c[0]), e01 = tanh_fast(a1c[1]);
            float e02 = tanh_fast(a1c[2]), e03 = tanh_fast(a1c[3]);

            float rp1 = d00 + d01 + e00 + e01;
            float rp2 = d02 + d03 + e02 + e03;
#pragma unroll
            for (int off = 1; off <= 2; off <<= 1) {
                rp1 += __shfl_xor_sync(0xffffffffu, rp1, off);
                rp2 += __shfl_xor_sync(0xffffffffu, rp2, off);
            }
            if (r == 0) {
                rowP[g * 64 + mt * 16 + q]     = rp1;
                rowP[g * 64 + mt * 16 + q + 8] = rp2;
            }

            float cp0 = d00 + d02;
            float cp1 = d01 + d03;
            float cp2 = e00 + e02;
            float cp3 = e01 + e03;
#pragma unroll
            for (int off = 4; off <= 16; off <<= 1) {
                cp0 += __shfl_xor_sync(0xffffffffu, cp0, off);
                cp1 += __shfl_xor_sync(0xffffffffu, cp1, off);
                cp2 += __shfl_xor_sync(0xffffffffu, cp2, off);
                cp3 += __shfl_xor_sync(0xffffffffu, cp3, off);
            }
            if (q == 0) {
                colP[mt * 64 + g * 16 + 2 * r]         = cp0;
                colP[mt * 64 + g * 16 + 2 * r + 1]     = cp1;
                colP[mt * 64 + g * 16 + 8 + 2 * r]     = cp2;
                colP[mt * 64 + g * 16 + 8 + 2 * r + 1] = cp3;
            }
        }
        __syncthreads();

        // --- softmax over 64 (warp 0 rows, warp 1 cols) ---
        if (tid < 64) {
            int l = tid & 31;
            const float* P = (tid < 32) ? rowP : colP;
            float* dst     = (tid < 32) ? rows_w : cols_w;
            float v0 = P[l]      + P[64 + l]      + P[128 + l]      + P[192 + l];
            float v1 = P[l + 32] + P[64 + l + 32] + P[128 + l + 32] + P[192 + l + 32];
            v0 *= (1.f / 64.f);
            v1 *= (1.f / 64.f);
            float mx = fmaxf(v0, v1);
#pragma unroll
            for (int off = 16; off; off >>= 1)
                mx = fmaxf(mx, __shfl_xor_sync(0xffffffffu, mx, off));
            float e0 = __expf(v0 - mx);
            float e1 = __expf(v1 - mx);
            float s = e0 + e1;
#pragma unroll
            for (int off = 16; off; off >>= 1)
                s += __shfl_xor_sync(0xffffffffu, s, off);
            float inv = 1.f / s;
            dst[l]      = e0 * inv;
            dst[l + 32] = e1 * inv;
        }
        __syncthreads();

        // --- s1 = rows_w @ AW, newB = cols_w @ B; con = s1 . newB ---
        {
            const int d = tid & 127;
            const int q = tid >> 7;
            float s1p = 0.f, nbp = 0.f;
            const float* gW = g_AW + (q * 16) * D_DIM + d;
            const float* sb = sB + (q * 16) * PAD_STRIDE + d;
#pragma unroll
            for (int k = 0; k < 16; k++) {
                s1p = fmaf(rows_w[q * 16 + k], __ldg(gW + k * D_DIM), s1p);
                nbp = fmaf(cols_w[q * 16 + k], sb[k * PAD_STRIDE], nbp);
            }
            scratch[tid]       = s1p;
            scratch[512 + tid] = nbp;
        }
        __syncthreads();
        if (tid < D_DIM) {
            float s1 = scratch[tid] + scratch[128 + tid]
                     + scratch[256 + tid] + scratch[384 + tid];
            float nb = scratch[512 + tid] + scratch[640 + tid]
                     + scratch[768 + tid] + scratch[896 + tid];
            float pc = s1 * nb;
#pragma unroll
            for (int off = 16; off; off >>= 1)
                pc += __shfl_down_sync(0xffffffffu, pc, off);
            if (lane == 0) atomicAdd(&sc[3], pc);
        }
        __syncthreads();

        if (tid == 0) {
            float n1 = fmaxf(sqrtf(sc[1]), EPS);
            float n2 = fmaxf(sqrtf(sc[2]), EPS);
            float str_score = sc[0] / (n1 * n2);
            float con_score = sc[3] + b_bi[0];
            out[cc] = 0.5f * str_score + 0.5f * con_score;
        }
        __syncthreads();   // protect rowP/colP/scratch before next candidate
    }
}

// ---------------------------------------------------------------------------
extern "C" void kernel_launch(void* const* d_in, const int* in_sizes, int n_in,
                              void* d_out, int out_size) {
    const float* table   = (const float*)d_in[0];
    const float* str_t1  = (const float*)d_in[1];
    const float* str_t2s = (const float*)d_in[2];
    const float* att_mat = (const float*)d_in[3];
    const float* W_bi    = (const float*)d_in[4];
    const float* b_bi    = (const float*)d_in[5];
    const int*   t1_ctx  = (const int*)d_in[6];
    const int*   t2_ctx  = (const int*)d_in[7];
    float* out = (float*)d_out;

    cudaFuncSetAttribute(cand_kernel,
                         cudaFuncAttributeMaxDynamicSharedMemorySize,
                         SMEM_FLOATS * sizeof(float));

    prep_kernel<<<128, 512>>>(table, att_mat, W_bi, t1_ctx);
    cand_kernel<<<GRID_B, 512, SMEM_FLOATS * sizeof(float)>>>(
        table, str_t1, str_t2s, b_bi, t2_ctx, out);
}

// round 17
// speedup vs baseline: 1.0644x; 1.0644x over previous
#include <cuda_runtime.h>
#include <math.h>
#include <stdint.h>

#define K_CTX 64
#define D_DIM 128
#define C_CAND 256
#define DS 200
#define EPS 1e-8f

// Padded row stride: 132 floats (528B, 16B-aligned); MMA frag loads conflict-free.
#define PAD_STRIDE 132
#define ROW_BYTES (PAD_STRIDE * 4)      // 528
#define AM_FLOATS (K_CTX * PAD_STRIDE)  // 8448

// Scratch (device globals)
__device__ __align__(16) float g_AM[AM_FLOATS];         // padded, tf32-rounded
__device__ __align__(16) float g_AW[K_CTX * D_DIM];     // A @ W, flat fp32

// smem: sAM(8448) sB(8448) rowP(256) colP(256) rows_w(64) cols_w(64)
//       scal(4) mbars(4)   (sAM doubles as tail scratch)
#define SMEM_FLOATS (AM_FLOATS + AM_FLOATS + 256 + 256 + 64 + 64 + 4 + 4)

__device__ __forceinline__ uint32_t smem_u32(const void* p) {
    return (uint32_t)__cvta_generic_to_shared(p);
}
__device__ __forceinline__ void mbar_init(uint32_t mbar, uint32_t cnt) {
    asm volatile("mbarrier.init.shared.b64 [%0], %1;" :: "r"(mbar), "r"(cnt) : "memory");
}
__device__ __forceinline__ void mbar_expect_tx(uint32_t mbar, uint32_t bytes) {
    asm volatile("mbarrier.arrive.expect_tx.shared.b64 _, [%0], %1;"
                 :: "r"(mbar), "r"(bytes) : "memory");
}
__device__ __forceinline__ void mbar_wait(uint32_t mbar, uint32_t parity) {
    uint32_t done;
    asm volatile(
        "{\n\t.reg .pred p;\n\t"
        "mbarrier.try_wait.parity.acquire.cta.shared::cta.b64 p, [%1], %2;\n\t"
        "selp.b32 %0, 1, 0, p;\n\t}"
        : "=r"(done) : "r"(mbar), "r"(parity) : "memory");
    if (!done) {
        asm volatile(
            "{\n\t.reg .pred P1;\n\t"
            "WAIT_LOOP_%=:\n\t"
            "mbarrier.try_wait.parity.acquire.cta.shared::cta.b64 P1, [%0], %1, 0x989680;\n\t"
            "@P1 bra.uni WAIT_DONE_%=;\n\t"
            "bra.uni WAIT_LOOP_%=;\n\t"
            "WAIT_DONE_%=:\n\t}"
            :: "r"(mbar), "r"(parity) : "memory");
    }
}
__device__ __forceinline__ void bulk_g2s(uint32_t dst_smem, const void* src_gmem,
                                         uint32_t bytes, uint32_t mbar) {
    asm volatile(
        "cp.async.bulk.shared::cluster.global.mbarrier::complete_tx::bytes "
        "[%0], [%1], %2, [%3];"
        :: "r"(dst_smem), "l"(src_gmem), "r"(bytes), "r"(mbar) : "memory");
}
__device__ __forceinline__ float tanh_fast(float x) {
    float y;
    asm("tanh.approx.f32 %0, %1;" : "=f"(y) : "f"(x));
    return y;
}
__device__ __forceinline__ uint32_t to_tf32(float x) {
    uint32_t y;
    asm("cvt.rna.tf32.f32 %0, %1;" : "=r"(y) : "f"(x));
    return y;
}
__device__ __forceinline__ void mma_tf32(float* c, uint32_t a0, uint32_t a1,
                                         uint32_t a2, uint32_t a3,
                                         uint32_t b0, uint32_t b1) {
    asm volatile(
        "mma.sync.aligned.m16n8k8.row.col.f32.tf32.tf32.f32 "
        "{%0,%1,%2,%3}, {%4,%5,%6,%7}, {%8,%9}, {%0,%1,%2,%3};"
        : "+f"(c[0]), "+f"(c[1]), "+f"(c[2]), "+f"(c[3])
        : "r"(a0), "r"(a1), "r"(a2), "r"(a3), "r"(b0), "r"(b1));
}

// ---------------------------------------------------------------------------
// Kernel 1: prep — grid 128. Block b: k = b&63; mode = b>>6 (0: AM, 1: AW).
// ---------------------------------------------------------------------------
__global__ __launch_bounds__(512, 2)
void prep_kernel(const float* __restrict__ table,
                 const float* __restrict__ att_mat,
                 const float* __restrict__ W,
                 const int* __restrict__ t1_ctx) {
    __shared__ float arow[D_DIM];
    __shared__ float part[512];
    const int k    = blockIdx.x & 63;
    const int mode = blockIdx.x >> 6;
    const int tid  = threadIdx.x;

    if (tid < D_DIM)
        arow[tid] = table[(long long)t1_ctx[k] * D_DIM + tid];
    __syncthreads();
    {
        const int d = tid & 127;
        const int q = tid >> 7;
        const float* M  = (mode == 0) ? att_mat : W;
        const float* mp = M + (q * 32) * D_DIM + d;
        const float* ar = arow + q * 32;
        float acc = 0.f;
#pragma unroll
        for (int e = 0; e < 32; e++)
            acc = fmaf(ar[e], mp[e * D_DIM], acc);
        part[tid] = acc;
    }
    __syncthreads();
    if (tid < D_DIM) {
        float v = part[tid] + part[D_DIM + tid]
                + part[2 * D_DIM + tid] + part[3 * D_DIM + tid];
        if (mode == 0)
            g_AM[k * PAD_STRIDE + tid] = __uint_as_float(to_tf32(v));
        else
            g_AW[k * D_DIM + tid] = v;
    }
}

// ---------------------------------------------------------------------------
// Kernel 2: main — grid 256, block 512, 3/SM. sim via tf32 MMA; bilinear
// folded through g_AW; phase 6 fully float4-vectorized.
// ---------------------------------------------------------------------------
__global__ __launch_bounds__(512, 3)
void cand_kernel(const float* __restrict__ table,
                 const float* __restrict__ str_t1,
                 const float* __restrict__ str_t2s,
                 const float* __restrict__ b_bi,
                 const int* __restrict__ t2_ctx,
                 float* __restrict__ out) {
    extern __shared__ __align__(16) float sm[];
    float* sAM    = sm;                        // [64][132] tf32 AM (+scratch)
    float* sB     = sAM + AM_FLOATS;           // [64][132] fp32 B
    float* rowP   = sB + AM_FLOATS;            // [4][64]
    float* colP   = rowP + 256;                // [4][64]
    float* rows_w = colP + 256;                // 64
    float* cols_w = rows_w + K_CTX;            // 64
    float* scal   = cols_w + K_CTX;            // 4
    uint64_t* mbars = (uint64_t*)(scal + 4);   // [0]=gather, [1]=AM stage

    const int c    = blockIdx.x;
    const int tid  = threadIdx.x;
    const int wid  = tid >> 5;
    const int lane = tid & 31;
    const uint32_t mbar_g = smem_u32(&mbars[0]);
    const uint32_t mbar_a = smem_u32(&mbars[1]);

    // --- phase 0: init mbarriers + zero accumulators ---
    if (tid == 0) {
        mbar_init(mbar_g, 1);
        mbar_init(mbar_a, 1);
        mbar_expect_tx(mbar_g, K_CTX * D_DIM * 4);
        mbar_expect_tx(mbar_a, AM_FLOATS * 4);
    }
    if (tid < 4) scal[tid] = 0.f;
    __syncthreads();

    // --- phase 1: issue all async copies (graph edge guarantees g_AM/g_AW) ---
    const int* ctx = t2_ctx + c * K_CTX;
    if (tid < K_CTX) {
        bulk_g2s(smem_u32(sB) + tid * ROW_BYTES,
                 table + (long long)ctx[tid] * D_DIM,
                 D_DIM * 4, mbar_g);
    } else if (tid == K_CTX) {
        bulk_g2s(smem_u32(sAM), g_AM, AM_FLOATS * 4, mbar_a);
    }

    // --- phase 2: string cosine partials ---
    {
        float pd = 0.f, p1 = 0.f, p2 = 0.f;
        if (tid < DS) {
            float x1 = str_t1[tid];
            float x2 = str_t2s[c * DS + tid];
            pd = x1 * x2; p1 = x1 * x1; p2 = x2 * x2;
        }
#pragma unroll
        for (int off = 16; off; off >>= 1) {
            pd += __shfl_down_sync(0xffffffffu, pd, off);
            p1 += __shfl_down_sync(0xffffffffu, p1, off);
            p2 += __shfl_down_sync(0xffffffffu, p2, off);
        }
        if (lane == 0 && wid < 7) {
            atomicAdd(&scal[0], pd);
            atomicAdd(&scal[1], p1);
            atomicAdd(&scal[2], p2);
        }
    }

    // --- phase 3: wait transfers ---
    mbar_wait(mbar_g, 0);
    mbar_wait(mbar_a, 0);
    __syncthreads();

    // --- phase 4: sim = tanh(AM @ B^T) via m16n8k8 tf32 MMA ---
    {
        const int mt = wid & 3;
        const int g  = wid >> 2;
        const int q  = lane >> 2;
        const int r  = lane & 3;
        const float* Ab  = sAM + mt * 16 * PAD_STRIDE;
        const float* Bb0 = sB + (g * 16) * PAD_STRIDE;
        const float* Bb1 = Bb0 + 8 * PAD_STRIDE;

        float c0[4] = {0.f, 0.f, 0.f, 0.f};
        float c1[4] = {0.f, 0.f, 0.f, 0.f};

#pragma unroll
        for (int ks = 0; ks < 16; ks++) {
            const int kb = ks * 8;
            uint32_t a0 = __float_as_uint(Ab[q * PAD_STRIDE + kb + r]);
            uint32_t a1 = __float_as_uint(Ab[(q + 8) * PAD_STRIDE + kb + r]);
            uint32_t a2 = __float_as_uint(Ab[q * PAD_STRIDE + kb + r + 4]);
            uint32_t a3 = __float_as_uint(Ab[(q + 8) * PAD_STRIDE + kb + r + 4]);
            uint32_t b00 = to_tf32(Bb0[q * PAD_STRIDE + kb + r]);
            uint32_t b01 = to_tf32(Bb0[q * PAD_STRIDE + kb + r + 4]);
            uint32_t b10 = to_tf32(Bb1[q * PAD_STRIDE + kb + r]);
            uint32_t b11 = to_tf32(Bb1[q * PAD_STRIDE + kb + r + 4]);

            mma_tf32(c0, a0, a1, a2, a3, b00, b01);
            mma_tf32(c1, a0, a1, a2, a3, b10, b11);
        }

        float d00 = tanh_fast(c0[0]), d01 = tanh_fast(c0[1]);
        float d02 = tanh_fast(c0[2]), d03 = tanh_fast(c0[3]);
        float e00 = tanh_fast(c1[0]), e01 = tanh_fast(c1[1]);
        float e02 = tanh_fast(c1[2]), e03 = tanh_fast(c1[3]);

        // row partials: reduce over r (lane bits 0-1)
        float rp1 = d00 + d01 + e00 + e01;
        float rp2 = d02 + d03 + e02 + e03;
#pragma unroll
        for (int off = 1; off <= 2; off <<= 1) {
            rp1 += __shfl_xor_sync(0xffffffffu, rp1, off);
            rp2 += __shfl_xor_sync(0xffffffffu, rp2, off);
        }
        if (r == 0) {
            rowP[g * 64 + mt * 16 + q]     = rp1;
            rowP[g * 64 + mt * 16 + q + 8] = rp2;
        }

        // col partials: reduce over q (lane bits 2-4)
        float cp0 = d00 + d02;
        float cp1 = d01 + d03;
        float cp2 = e00 + e02;
        float cp3 = e01 + e03;
#pragma unroll
        for (int off = 4; off <= 16; off <<= 1) {
            cp0 += __shfl_xor_sync(0xffffffffu, cp0, off);
            cp1 += __shfl_xor_sync(0xffffffffu, cp1, off);
            cp2 += __shfl_xor_sync(0xffffffffu, cp2, off);
            cp3 += __shfl_xor_sync(0xffffffffu, cp3, off);
        }
        if (q == 0) {
            colP[mt * 64 + g * 16 + 2 * r]         = cp0;
            colP[mt * 64 + g * 16 + 2 * r + 1]     = cp1;
            colP[mt * 64 + g * 16 + 8 + 2 * r]     = cp2;
            colP[mt * 64 + g * 16 + 8 + 2 * r + 1] = cp3;
        }
    }
    __syncthreads();

    // --- phase 5: softmax over 64 (warp 0 rows, warp 1 cols; fold partials)
    if (tid < 64) {
        int l = tid & 31;
        const float* P = (tid < 32) ? rowP : colP;
        float* dst     = (tid < 32) ? rows_w : cols_w;
        float v0 = P[l]      + P[64 + l]      + P[128 + l]      + P[192 + l];
        float v1 = P[l + 32] + P[64 + l + 32] + P[128 + l + 32] + P[192 + l + 32];
        v0 *= (1.f / 64.f);
        v1 *= (1.f / 64.f);
        float mx = fmaxf(v0, v1);
#pragma unroll
        for (int off = 16; off; off >>= 1)
            mx = fmaxf(mx, __shfl_xor_sync(0xffffffffu, mx, off));
        float e0 = __expf(v0 - mx);
        float e1 = __expf(v1 - mx);
        float s = e0 + e1;
#pragma unroll
        for (int off = 16; off; off >>= 1)
            s += __shfl_xor_sync(0xffffffffu, s, off);
        float inv = 1.f / s;
        dst[l]      = e0 * inv;
        dst[l + 32] = e1 * inv;
    }
    __syncthreads();

    // --- phase 6: s1 = rows_w @ AW, newB = cols_w @ B, con = s1.newB ---
    // Vectorized: warp q' (tid>>5) owns k rows [4q',4q'+4); lane = float4 col.
    {
        const int qp = tid >> 5;           // 0..15 (warp-uniform)
        const int v  = lane;               // float4 column 0..31
        float4 s1p = make_float4(0.f, 0.f, 0.f, 0.f);
        float4 nbp = make_float4(0.f, 0.f, 0.f, 0.f);
#pragma unroll
        for (int kk = 0; kk < 4; kk++) {
            const int k = qp * 4 + kk;
            const float rw = rows_w[k];    // warp-uniform broadcast
            const float cw = cols_w[k];
            float4 aw = __ldg((const float4*)(g_AW + k * D_DIM) + v);
            float4 bb = *((const float4*)(sB + k * PAD_STRIDE) + v);
            s1p.x = fmaf(rw, aw.x, s1p.x); s1p.y = fmaf(rw, aw.y, s1p.y);
            s1p.z = fmaf(rw, aw.z, s1p.z); s1p.w = fmaf(rw, aw.w, s1p.w);
            nbp.x = fmaf(cw, bb.x, nbp.x); nbp.y = fmaf(cw, bb.y, nbp.y);
            nbp.z = fmaf(cw, bb.z, nbp.z); nbp.w = fmaf(cw, bb.w, nbp.w);
        }
        ((float4*)sAM)[qp * 32 + v]       = s1p;   // sAM free after sim
        ((float4*)sAM)[512 + qp * 32 + v] = nbp;
    }
    __syncthreads();
    if (tid < D_DIM) {
        // fold 16 k-group partials (stride 128 floats), then dot
        float s1 = 0.f, nb = 0.f;
#pragma unroll
        for (int q = 0; q < 16; q++) {
            s1 += sAM[q * 128 + tid];
            nb += sAM[2048 + q * 128 + tid];
        }
        float pc = s1 * nb;
#pragma unroll
        for (int off = 16; off; off >>= 1)
            pc += __shfl_down_sync(0xffffffffu, pc, off);
        if (lane == 0) atomicAdd(&scal[3], pc);
    }
    __syncthreads();

    if (tid == 0) {
        float n1 = fmaxf(sqrtf(scal[1]), EPS);
        float n2 = fmaxf(sqrtf(scal[2]), EPS);
        float str_score = scal[0] / (n1 * n2);
        float con_score = scal[3] + b_bi[0];
        out[c] = 0.5f * str_score + 0.5f * con_score;
    }
}

// ---------------------------------------------------------------------------
extern "C" void kernel_launch(void* const* d_in, const int* in_sizes, int n_in,
                              void* d_out, int out_size) {
    const float* table   = (const float*)d_in[0];
    const float* str_t1  = (const float*)d_in[1];
    const float* str_t2s = (const float*)d_in[2];
    const float* att_mat = (const float*)d_in[3];
    const float* W_bi    = (const float*)d_in[4];
    const float* b_bi    = (const float*)d_in[5];
    const int*   t1_ctx  = (const int*)d_in[6];
    const int*   t2_ctx  = (const int*)d_in[7];
    float* out = (float*)d_out;

    cudaFuncSetAttribute(cand_kernel,
                         cudaFuncAttributeMaxDynamicSharedMemorySize,
                         SMEM_FLOATS * sizeof(float));

    prep_kernel<<<128, 512>>>(table, att_mat, W_bi, t1_ctx);
    cand_kernel<<<C_CAND, 512, SMEM_FLOATS * sizeof(float)>>>(
        table, str_t1, str_t2s, b_bi, t2_ctx, out);
}